// round 14
// baseline (speedup 1.0000x reference)
#include <cuda_runtime.h>
#include <cuda_bf16.h>
#include <mma.h>
#include <math.h>

using namespace nvcuda;

#define BB 16
#define NN 4096
#define CC 128
#define C2 256
#define NUM_NODES 65536
#define EDGES 2097152

// ---------------- device scratch (static, no allocs) ----------------
static __device__ int   g_is64;
static __device__ int   g_count[NUM_NODES];
static __device__ int   g_off[NUM_NODES + 1];
static __device__ int   g_cursor[NUM_NODES];
static __device__ int   g_blksum[256];
static __device__ int   g_src[EDGES];
static __device__ float g_agg[NUM_NODES * CC];
static __device__ float g_sage[NUM_NODES * CC];
static __device__ uint4 g_w1h4[CC * 384 / 8];        // conv1 bf16 hi, [co][k'=ci*3+k]
static __device__ uint4 g_w1l4[CC * 384 / 8];
static __device__ uint4 g_wsh4[CC * 256 / 8];        // sage [Wl|Wr] bf16 hi, [co][k'=256]
static __device__ uint4 g_wsl4[CC * 256 / 8];
static __device__ uint4 g_w2h4[C2 * 768 / 8];        // conv2 bf16 hi, [co][k'=ci*3+k]
static __device__ uint4 g_w2l4[C2 * 768 / 8];
static __device__ float g_sum1[CC],  g_ssq1[CC];
static __device__ float g_max1[BB * CC], g_min1[BB * CC];
static __device__ float g_sum2[C2],  g_ssq2[C2];
static __device__ float g_max2[BB * C2], g_min2[BB * C2];

__device__ __forceinline__ float fNINF() { return __int_as_float(0xff800000u); }
__device__ __forceinline__ float fPINF() { return __int_as_float(0x7f800000u); }

__device__ __forceinline__ void atomicMaxF(float* a, float v) {
    if (v >= 0.f) atomicMax((int*)a, __float_as_int(v));
    else          atomicMin((unsigned int*)a, __float_as_uint(v));
}
__device__ __forceinline__ void atomicMinF(float* a, float v) {
    if (v >= 0.f) atomicMin((int*)a, __float_as_int(v));
    else          atomicMax((unsigned int*)a, __float_as_uint(v));
}

// split 2 floats into packed bf16 hi (truncation) + bf16 lo (rounded residual)
__device__ __forceinline__ void split2(float x0, float x1, unsigned& hpack, unsigned& lpack) {
    unsigned u0 = __float_as_uint(x0), u1 = __float_as_uint(x1);
    hpack = __byte_perm(u0, u1, 0x7632);               // {u1.hi16, u0.hi16}
    float h0 = __uint_as_float(u0 & 0xFFFF0000u);
    float h1 = __uint_as_float(u1 & 0xFFFF0000u);
    float l0 = x0 - h0, l1 = x1 - h1;                  // exact
    asm("cvt.rn.bf16x2.f32 %0, %1, %2;" : "=r"(lpack) : "f"(l1), "f"(l0));
}

// ---------------- merged setup: dtype sniff + scratch init + weight prep ----------------
__global__ void k_setup(const unsigned int* __restrict__ topo_u32,
                        const float* __restrict__ w1, const float* __restrict__ Wl,
                        const float* __restrict__ Wr, const float* __restrict__ w2) {
    int i = blockIdx.x * blockDim.x + threadIdx.x;
    if (i == 0) {
        int is64 = 1;
        #pragma unroll 1
        for (int j = 0; j < 32; j++) {
            if (topo_u32[2 * j + 1] != 0u) { is64 = 0; break; }
        }
        g_is64 = is64;
    }
    if (i < NUM_NODES) g_count[i] = 0;
    if (i < CC) { g_sum1[i] = 0.f; g_ssq1[i] = 0.f; }
    if (i < C2) { g_sum2[i] = 0.f; g_ssq2[i] = 0.f; }
    if (i < BB * CC) { g_max1[i] = fNINF(); g_min1[i] = fPINF(); }
    if (i < BB * C2) { g_max2[i] = fNINF(); g_min2[i] = fPINF(); }
    if (i < CC * 384) {
        float v = w1[i];
        __nv_bfloat16 hi = __float2bfloat16(v);
        __nv_bfloat16 lo = __float2bfloat16(v - __bfloat162float(hi));
        ((__nv_bfloat16*)g_w1h4)[i] = hi;
        ((__nv_bfloat16*)g_w1l4)[i] = lo;
    }
    if (i < CC * 256) {
        int co = i >> 8, kp = i & 255;
        float v = (kp < CC) ? Wl[co * CC + kp] : Wr[co * CC + (kp - CC)];
        __nv_bfloat16 hi = __float2bfloat16(v);
        __nv_bfloat16 lo = __float2bfloat16(v - __bfloat162float(hi));
        ((__nv_bfloat16*)g_wsh4)[i] = hi;
        ((__nv_bfloat16*)g_wsl4)[i] = lo;
    }
    if (i < C2 * 768) {
        float v = w2[i];
        __nv_bfloat16 hi = __float2bfloat16(v);
        __nv_bfloat16 lo = __float2bfloat16(v - __bfloat162float(hi));
        ((__nv_bfloat16*)g_w2h4)[i] = hi;
        ((__nv_bfloat16*)g_w2l4)[i] = lo;
    }
}

// ---------------- CSR build (2 edges per thread) ----------------
__global__ void k_hist(const void* __restrict__ topo) {
    int p = blockIdx.x * blockDim.x + threadIdx.x;
    if (p * 2 >= EDGES) return;
    if (g_is64) {
        longlong2 d = __ldg((const longlong2*)((const long long*)topo + EDGES) + p);
        atomicAdd(&g_count[(int)d.x], 1);
        atomicAdd(&g_count[(int)d.y], 1);
    } else {
        int2 d = __ldg((const int2*)((const int*)topo + EDGES) + p);
        atomicAdd(&g_count[d.x], 1);
        atomicAdd(&g_count[d.y], 1);
    }
}

__global__ void k_scan1() {
    __shared__ int sh[256];
    int b = blockIdx.x, t = threadIdx.x;
    int i = b * 256 + t;
    int c = g_count[i];
    sh[t] = c;
    __syncthreads();
    for (int ofs = 1; ofs < 256; ofs <<= 1) {
        int v = (t >= ofs) ? sh[t - ofs] : 0;
        __syncthreads();
        sh[t] += v;
        __syncthreads();
    }
    g_off[i] = sh[t] - c;
    if (t == 255) g_blksum[b] = sh[255];
}

__global__ void k_scan2() {
    __shared__ int sh[256];
    int t = threadIdx.x;
    int c = g_blksum[t];
    sh[t] = c;
    __syncthreads();
    for (int ofs = 1; ofs < 256; ofs <<= 1) {
        int v = (t >= ofs) ? sh[t - ofs] : 0;
        __syncthreads();
        sh[t] += v;
        __syncthreads();
    }
    g_blksum[t] = sh[t] - c;
}

__global__ void k_scan3() {
    int b = blockIdx.x, t = threadIdx.x;
    int i = b * 256 + t;
    int v = g_off[i] + g_blksum[b];
    g_off[i] = v;
    g_cursor[i] = v;
    if (i == NUM_NODES - 1) g_off[NUM_NODES] = EDGES;
}

__global__ void k_scatter(const void* __restrict__ topo) {
    int p = blockIdx.x * blockDim.x + threadIdx.x;
    if (p * 2 >= EDGES) return;
    int s0, s1, d0, d1;
    if (g_is64) {
        longlong2 s = __ldg((const longlong2*)topo + p);
        longlong2 d = __ldg((const longlong2*)((const long long*)topo + EDGES) + p);
        s0 = (int)s.x; s1 = (int)s.y; d0 = (int)d.x; d1 = (int)d.y;
    } else {
        int2 s = __ldg((const int2*)topo + p);
        int2 d = __ldg((const int2*)((const int*)topo + EDGES) + p);
        s0 = s.x; s1 = s.y; d0 = d.x; d1 = d.y;
    }
    int pos0 = atomicAdd(&g_cursor[d0], 1);
    g_src[pos0] = s0;
    int pos1 = atomicAdd(&g_cursor[d1], 1);
    g_src[pos1] = s1;
}

// ---------------- fused agg + sage: gather-max, then WMMA GEMM + bias + L2-norm ----------------
#define SLDA 72
#define SLDB 136
#define SOFF_X   0         // 128 x 65 floats = 33280B
#define SOFF_AH  33280
#define SOFF_AL  51712
#define SOFF_BH  70144
#define SOFF_BL  87552
#define SM_SAGE_TOTAL 104960
__global__ __launch_bounds__(256) void k_aggsage(const float* __restrict__ feat,
                                                 const float* __restrict__ bl) {
    extern __shared__ char smc[];
    float* shX = (float*)(smc + SOFF_X);
    __nv_bfloat16* shAh = (__nv_bfloat16*)(smc + SOFF_AH);
    __nv_bfloat16* shAl = (__nv_bfloat16*)(smc + SOFF_AL);
    __nv_bfloat16* shBh = (__nv_bfloat16*)(smc + SOFF_BH);
    __nv_bfloat16* shBl = (__nv_bfloat16*)(smc + SOFF_BL);

    int tid = threadIdx.x;
    int wid = tid >> 5, lane = tid & 31;
    int n0 = blockIdx.x * 128;
    int wy = wid & 3, wx = wid >> 2;

    // ---- phase 1: max-aggregate 16 nodes per warp, write g_agg (read back below, L1-hot) ----
    for (int t = 0; t < 16; t++) {
        int n = n0 + wid * 16 + t;
        int beg = g_off[n], end = g_off[n + 1];
        float4 acc = make_float4(fNINF(), fNINF(), fNINF(), fNINF());
        int i = beg;
        for (; i + 4 <= end; i += 4) {
            int s0 = g_src[i], s1 = g_src[i + 1], s2 = g_src[i + 2], s3 = g_src[i + 3];
            float4 v0 = __ldg(((const float4*)(feat + (size_t)s0 * CC)) + lane);
            float4 v1 = __ldg(((const float4*)(feat + (size_t)s1 * CC)) + lane);
            float4 v2 = __ldg(((const float4*)(feat + (size_t)s2 * CC)) + lane);
            float4 v3 = __ldg(((const float4*)(feat + (size_t)s3 * CC)) + lane);
            acc.x = fmaxf(acc.x, fmaxf(fmaxf(v0.x, v1.x), fmaxf(v2.x, v3.x)));
            acc.y = fmaxf(acc.y, fmaxf(fmaxf(v0.y, v1.y), fmaxf(v2.y, v3.y)));
            acc.z = fmaxf(acc.z, fmaxf(fmaxf(v0.z, v1.z), fmaxf(v2.z, v3.z)));
            acc.w = fmaxf(acc.w, fmaxf(fmaxf(v0.w, v1.w), fmaxf(v2.w, v3.w)));
        }
        for (; i < end; i++) {
            int s0 = g_src[i];
            float4 v0 = __ldg(((const float4*)(feat + (size_t)s0 * CC)) + lane);
            acc.x = fmaxf(acc.x, v0.x);
            acc.y = fmaxf(acc.y, v0.y);
            acc.z = fmaxf(acc.z, v0.z);
            acc.w = fmaxf(acc.w, v0.w);
        }
        if (beg == end) acc = make_float4(0.f, 0.f, 0.f, 0.f);
        ((float4*)(g_agg + (size_t)n * CC))[lane] = acc;
    }
    __syncthreads();

    // ---- phase 2: sage GEMM ----
    wmma::fragment<wmma::accumulator, 16, 16, 16, float> facc[2][4];
    #pragma unroll
    for (int i = 0; i < 2; i++)
        #pragma unroll
        for (int j = 0; j < 4; j++) wmma::fill_fragment(facc[i][j], 0.f);

    for (int c = 0; c < 4; c++) {
        __syncthreads();
        const float* src = (c < 2) ? (g_agg + (size_t)n0 * CC + c * 64)
                                   : (feat + (size_t)n0 * CC + (c - 2) * 64);
        for (int idx = tid; idx < 128 * 16; idx += 256) {
            int n = idx >> 4, f = idx & 15;
            float4 v = *(const float4*)(src + (size_t)n * CC + f * 4);
            int o = n * 65 + f * 4;
            shX[o] = v.x; shX[o + 1] = v.y; shX[o + 2] = v.z; shX[o + 3] = v.w;
        }
        for (int idx = tid; idx < 1024; idx += 256) {
            int r = idx >> 3, q = idx & 7;
            int gidx = r * 32 + c * 8 + q;
            *(uint4*)(shAh + r * SLDA + q * 8) = g_wsh4[gidx];
            *(uint4*)(shAl + r * SLDA + q * 8) = g_wsl4[gidx];
        }
        __syncthreads();
        for (int idx = tid; idx < 64 * 64; idx += 256) {
            int kp = idx >> 6, p = idx & 63;
            int n = 2 * p;
            float x0 = shX[n * 65 + kp];
            float x1 = shX[(n + 1) * 65 + kp];
            unsigned hp, lp;
            split2(x0, x1, hp, lp);
            *(unsigned*)&shBh[kp * SLDB + n] = hp;
            *(unsigned*)&shBl[kp * SLDB + n] = lp;
        }
        __syncthreads();
        #pragma unroll 1
        for (int ks = 0; ks < 4; ks++) {
            wmma::fragment<wmma::matrix_a, 16, 16, 16, __nv_bfloat16, wmma::row_major> fah[2], fal[2];
            wmma::fragment<wmma::matrix_b, 16, 16, 16, __nv_bfloat16, wmma::row_major> fbh[4], fbl[4];
            #pragma unroll
            for (int i = 0; i < 2; i++) {
                const __nv_bfloat16* pa = shAh + (wy * 32 + i * 16) * SLDA + ks * 16;
                wmma::load_matrix_sync(fah[i], pa, SLDA);
                wmma::load_matrix_sync(fal[i], pa + (SOFF_AL - SOFF_AH) / 2, SLDA);
            }
            #pragma unroll
            for (int j = 0; j < 4; j++) {
                const __nv_bfloat16* pb = shBh + (ks * 16) * SLDB + wx * 64 + j * 16;
                wmma::load_matrix_sync(fbh[j], pb, SLDB);
                wmma::load_matrix_sync(fbl[j], pb + (SOFF_BL - SOFF_BH) / 2, SLDB);
            }
            #pragma unroll
            for (int i = 0; i < 2; i++)
                #pragma unroll
                for (int j = 0; j < 4; j++) {
                    wmma::mma_sync(facc[i][j], fah[i], fbh[j], facc[i][j]);
                    wmma::mma_sync(facc[i][j], fah[i], fbl[j], facc[i][j]);
                    wmma::mma_sync(facc[i][j], fal[i], fbh[j], facc[i][j]);
                }
        }
    }
    __syncthreads();

    float* ep = (float*)smc;
    #pragma unroll
    for (int i = 0; i < 2; i++)
        #pragma unroll
        for (int j = 0; j < 4; j++)
            wmma::store_matrix_sync(ep + (wy * 32 + i * 16) * 132 + wx * 64 + j * 16,
                                    facc[i][j], 132, wmma::mem_row_major);
    __syncthreads();

    if (tid < 128) {
        int n = tid;
        float ss = 0.f;
        #pragma unroll 4
        for (int co = 0; co < CC; co++) {
            float v = ep[co * 132 + n] + bl[co];
            ss += v * v;
        }
        float inv = 1.f / fmaxf(sqrtf(ss), 1e-12f);
        float* dst = g_sage + (size_t)(n0 + n) * CC;
        #pragma unroll 4
        for (int co = 0; co < CC; co += 4) {
            float4 o4;
            o4.x = (ep[(co + 0) * 132 + n] + bl[co + 0]) * inv;
            o4.y = (ep[(co + 1) * 132 + n] + bl[co + 1]) * inv;
            o4.z = (ep[(co + 2) * 132 + n] + bl[co + 2]) * inv;
            o4.w = (ep[(co + 3) * 132 + n] + bl[co + 3]) * inv;
            *(float4*)(dst + co) = o4;
        }
    }
}

// ---------------- unified conv kernel via WMMA, K' = ci*3+k ----------------
// blockIdx.z: 0,1 -> conv2 co-half; 2 -> conv1.
#define LDA 56
#define LDB 136
#define OFF_X   0        // 130 x 17 floats -> pad 8960
#define OFF_AHI 8960     // 128 x LDA bf16 = 14336B
#define OFF_ALO 23296
#define OFF_BHI 37632    // 48 x LDB bf16 = 13056B
#define OFF_BLO 50688    // end 63744
#define SM_CONVW_TOTAL 69632
#define OFF_EP  0        // epilogue: 8 warps x 32 x 68 floats = 69632B (aliases X/A/B after sync)

__global__ __launch_bounds__(256) void k_convs(const float* __restrict__ feat,
                                               const float* __restrict__ b1,
                                               const float* __restrict__ b2) {
    extern __shared__ char smc[];
    float* shX = (float*)(smc + OFF_X);
    __nv_bfloat16* shAhi = (__nv_bfloat16*)(smc + OFF_AHI);
    __nv_bfloat16* shAlo = (__nv_bfloat16*)(smc + OFF_ALO);
    __nv_bfloat16* shBhi = (__nv_bfloat16*)(smc + OFF_BHI);
    __nv_bfloat16* shBlo = (__nv_bfloat16*)(smc + OFF_BLO);

    int tid = threadIdx.x;
    int wid = tid >> 5, lane = tid & 31;
    int l0 = blockIdx.x * 128;
    int b  = blockIdx.y;
    int z  = blockIdx.z;
    bool isc1 = (z == 2);
    int NCH = isc1 ? 8 : 16;
    const uint4* wh4 = isc1 ? g_w1h4 : g_w2h4;
    const uint4* wl4 = isc1 ? g_w1l4 : g_w2l4;
    int co_basew = isc1 ? 0 : z * 128;
    int wstride  = isc1 ? 48 : 96;
    int wy = wid & 3, wx = wid >> 2;

    wmma::fragment<wmma::accumulator, 16, 16, 16, float> facc[2][4];
    #pragma unroll
    for (int i = 0; i < 2; i++)
        #pragma unroll
        for (int j = 0; j < 4; j++) wmma::fill_fragment(facc[i][j], 0.f);

    for (int c = 0; c < NCH; c++) {
        __syncthreads();
        int ci0 = c * 16;
        const float* src = (ci0 < CC) ? (g_sage + (size_t)b * NN * CC + ci0)
                                      : (feat + (size_t)b * NN * CC + (ci0 - CC));
        for (int idx = tid; idx < 130 * 4; idx += 256) {
            int row = idx >> 2, f = idx & 3;
            int gr = l0 + row; if (gr > NN - 1) gr = NN - 1;
            float4 v = *(const float4*)(src + (size_t)gr * CC + f * 4);
            int o = row * 17 + f * 4;
            shX[o] = v.x; shX[o + 1] = v.y; shX[o + 2] = v.z; shX[o + 3] = v.w;
        }
        for (int idx = tid; idx < 768; idx += 256) {
            int r = idx / 6, q = idx - r * 6;
            int gidx = (co_basew + r) * wstride + c * 6 + q;
            *(uint4*)(shAhi + r * LDA + q * 8) = wh4[gidx];
            *(uint4*)(shAlo + r * LDA + q * 8) = wl4[gidx];
        }
        __syncthreads();
        for (int idx = tid; idx < 48 * 64; idx += 256) {
            int kp = idx >> 6, p = idx & 63;
            int l = 2 * p;
            int ci = kp / 3, k = kp - ci * 3;
            float x0 = shX[(l + k) * 17 + ci];
            float x1 = shX[(l + 1 + k) * 17 + ci];
            unsigned hp, lp;
            split2(x0, x1, hp, lp);
            *(unsigned*)&shBhi[kp * LDB + l] = hp;
            *(unsigned*)&shBlo[kp * LDB + l] = lp;
        }
        __syncthreads();
        #pragma unroll 1
        for (int ks = 0; ks < 3; ks++) {
            wmma::fragment<wmma::matrix_a, 16, 16, 16, __nv_bfloat16, wmma::row_major> fah[2], fal[2];
            wmma::fragment<wmma::matrix_b, 16, 16, 16, __nv_bfloat16, wmma::row_major> fbh[4], fbl[4];
            #pragma unroll
            for (int i = 0; i < 2; i++) {
                const __nv_bfloat16* pa = shAhi + (wy * 32 + i * 16) * LDA + ks * 16;
                wmma::load_matrix_sync(fah[i], pa, LDA);
                wmma::load_matrix_sync(fal[i], pa + (OFF_ALO - OFF_AHI) / 2, LDA);
            }
            #pragma unroll
            for (int j = 0; j < 4; j++) {
                const __nv_bfloat16* pb = shBhi + (ks * 16) * LDB + wx * 64 + j * 16;
                wmma::load_matrix_sync(fbh[j], pb, LDB);
                wmma::load_matrix_sync(fbl[j], pb + (OFF_BLO - OFF_BHI) / 2, LDB);
            }
            #pragma unroll
            for (int i = 0; i < 2; i++)
                #pragma unroll
                for (int j = 0; j < 4; j++) {
                    wmma::mma_sync(facc[i][j], fah[i], fbh[j], facc[i][j]);
                    wmma::mma_sync(facc[i][j], fah[i], fbl[j], facc[i][j]);
                    wmma::mma_sync(facc[i][j], fal[i], fbh[j], facc[i][j]);
                }
        }
    }
    __syncthreads();

    float* ep = (float*)(smc + OFF_EP) + wid * (32 * 68);
    #pragma unroll
    for (int i = 0; i < 2; i++)
        #pragma unroll
        for (int j = 0; j < 4; j++)
            wmma::store_matrix_sync(ep + i * 16 * 68 + j * 16, facc[i][j], 68, wmma::mem_row_major);
    __syncwarp();

    {
        int col = wy * 32 + lane;
        float bias = isc1 ? b1[col] : b2[z * 128 + col];
        float mx = fNINF(), mn = fPINF(), s = 0.f, q = 0.f;
        #pragma unroll 4
        for (int l = 0; l < 64; l++) {
            int gl = l0 + wx * 64 + l;
            if (gl <= NN - 3) {
                float v = ep[lane * 68 + l] + bias;
                mx = fmaxf(mx, v); mn = fminf(mn, v);
                s += v; q += v * v;
            }
        }
        if (isc1) {
            int co = col;
            atomicAdd(&g_sum1[co], s);
            atomicAdd(&g_ssq1[co], q);
            atomicMaxF(&g_max1[b * CC + co], mx);
            atomicMinF(&g_min1[b * CC + co], mn);
        } else {
            int co = z * 128 + col;
            atomicAdd(&g_sum2[co], s);
            atomicAdd(&g_ssq2[co], q);
            atomicMaxF(&g_max2[b * C2 + co], mx);
            atomicMinF(&g_min2[b * C2 + co], mn);
        }
    }
}

// ---------------- finish: BN affine + relu + pool + linears + product ----------------
__global__ __launch_bounds__(512) void k_final(const float* __restrict__ g1, const float* __restrict__ be1,
                                               const float* __restrict__ g2, const float* __restrict__ be2,
                                               const float* __restrict__ l1w, const float* __restrict__ l1b,
                                               const float* __restrict__ l2w, const float* __restrict__ l2b,
                                               float* __restrict__ out) {
    __shared__ float p1[BB * CC];
    __shared__ float p2[BB * C2];
    int tid = threadIdx.x;
    const float cnt = (float)(BB * (NN - 2));

    for (int c = tid; c < CC; c += 512) {
        float m = g_sum1[c] / cnt;
        float v = g_ssq1[c] / cnt - m * m;
        float a = g1[c] * rsqrtf(fmaxf(v, 0.f) + 1e-5f);
        float o = be1[c] - a * m;
        for (int b = 0; b < BB; b++) {
            float x = (a >= 0.f) ? g_max1[b * CC + c] : g_min1[b * CC + c];
            p1[b * CC + c] = fmaxf(a * x + o, 0.f);
        }
    }
    for (int c = tid; c < C2; c += 512) {
        float m = g_sum2[c] / cnt;
        float v = g_ssq2[c] / cnt - m * m;
        float a = g2[c] * rsqrtf(fmaxf(v, 0.f) + 1e-5f);
        float o = be2[c] - a * m;
        for (int b = 0; b < BB; b++) {
            float x = (a >= 0.f) ? g_max2[b * C2 + c] : g_min2[b * C2 + c];
            p2[b * C2 + c] = fmaxf(a * x + o, 0.f);
        }
    }
    __syncthreads();
    if (tid < 32) {
        int b = tid >> 1, j = tid & 1;
        float s1 = l1b[j];
        for (int c = 0; c < CC; c++) s1 += p1[b * CC + c] * l1w[j * CC + c];
        float s2 = l2b[j];
        for (int c = 0; c < C2; c++) s2 += p2[b * C2 + c] * l2w[j * C2 + c];
        out[tid] = s1 * s2;
    }
}

// ---------------- host ----------------
extern "C" void kernel_launch(void* const* d_in, const int* in_sizes, int n_in,
                              void* d_out, int out_size) {
    const float* feature = (const float*)d_in[0];
    const void*  topo    = d_in[1];
    const float* lin_l_w = (const float*)d_in[3];
    const float* lin_l_b = (const float*)d_in[4];
    const float* lin_r_w = (const float*)d_in[5];
    const float* conv1_w = (const float*)d_in[6];
    const float* conv1_b = (const float*)d_in[7];
    const float* bn1_g   = (const float*)d_in[8];
    const float* bn1_b   = (const float*)d_in[9];
    const float* conv2_w = (const float*)d_in[10];
    const float* conv2_b = (const float*)d_in[11];
    const float* bn2_g   = (const float*)d_in[12];
    const float* bn2_b   = (const float*)d_in[13];
    const float* lin1_w  = (const float*)d_in[14];
    const float* lin1_b  = (const float*)d_in[15];
    const float* lin2_w  = (const float*)d_in[16];
    const float* lin2_b  = (const float*)d_in[17];
    float* out = (float*)d_out;

    cudaFuncSetAttribute(k_aggsage, cudaFuncAttributeMaxDynamicSharedMemorySize, SM_SAGE_TOTAL);
    cudaFuncSetAttribute(k_convs,   cudaFuncAttributeMaxDynamicSharedMemorySize, SM_CONVW_TOTAL);

    k_setup<<<768, 256>>>((const unsigned int*)topo, conv1_w, lin_l_w, lin_r_w, conv2_w);
    k_hist<<<EDGES / 512, 256>>>(topo);
    k_scan1<<<256, 256>>>();
    k_scan2<<<1, 256>>>();
    k_scan3<<<256, 256>>>();
    k_scatter<<<EDGES / 512, 256>>>(topo);
    k_aggsage<<<NUM_NODES / 128, 256, SM_SAGE_TOTAL>>>(feature, lin_l_b);
    k_convs<<<dim3(NN / 128, BB, 3), 256, SM_CONVW_TOTAL>>>(feature, conv1_b, conv2_b);
    k_final<<<1, 512>>>(bn1_g, bn1_b, bn2_g, bn2_b,
                        lin1_w, lin1_b, lin2_w, lin2_b, out);
}

// round 16
// speedup vs baseline: 1.1097x; 1.1097x over previous
#include <cuda_runtime.h>
#include <cuda_bf16.h>
#include <mma.h>
#include <math.h>

using namespace nvcuda;

#define BB 16
#define NN 4096
#define CC 128
#define C2 256
#define NUM_NODES 65536
#define EDGES 2097152

// ---------------- device scratch (static, no allocs) ----------------
static __device__ int   g_is64;
static __device__ int   g_count[NUM_NODES];
static __device__ int   g_off[NUM_NODES + 1];
static __device__ int   g_cursor[NUM_NODES];
static __device__ int   g_blksum[256];
static __device__ int   g_src[EDGES];
static __device__ float g_agg[NUM_NODES * CC];
static __device__ float g_sage[NUM_NODES * CC];
static __device__ uint4 g_w1h4[CC * 384 / 8];        // conv1 bf16 hi, [co][k'=ci*3+k]
static __device__ uint4 g_w1l4[CC * 384 / 8];
static __device__ uint4 g_wsh4[CC * 256 / 8];        // sage [Wl|Wr] bf16 hi, [co][k'=256]
static __device__ uint4 g_wsl4[CC * 256 / 8];
static __device__ uint4 g_w2h4[C2 * 768 / 8];        // conv2 bf16 hi, [co][k'=ci*3+k]
static __device__ uint4 g_w2l4[C2 * 768 / 8];
static __device__ float g_sum1[CC],  g_ssq1[CC];
static __device__ float g_max1[BB * CC], g_min1[BB * CC];
static __device__ float g_sum2[C2],  g_ssq2[C2];
static __device__ float g_max2[BB * C2], g_min2[BB * C2];

__device__ __forceinline__ float fNINF() { return __int_as_float(0xff800000u); }
__device__ __forceinline__ float fPINF() { return __int_as_float(0x7f800000u); }

__device__ __forceinline__ void atomicMaxF(float* a, float v) {
    if (v >= 0.f) atomicMax((int*)a, __float_as_int(v));
    else          atomicMin((unsigned int*)a, __float_as_uint(v));
}
__device__ __forceinline__ void atomicMinF(float* a, float v) {
    if (v >= 0.f) atomicMin((int*)a, __float_as_int(v));
    else          atomicMax((unsigned int*)a, __float_as_uint(v));
}

// split 2 floats into packed bf16 hi (truncation) + bf16 lo (rounded residual)
__device__ __forceinline__ void split2(float x0, float x1, unsigned& hpack, unsigned& lpack) {
    unsigned u0 = __float_as_uint(x0), u1 = __float_as_uint(x1);
    hpack = __byte_perm(u0, u1, 0x7632);               // {u1.hi16, u0.hi16}
    float h0 = __uint_as_float(u0 & 0xFFFF0000u);
    float h1 = __uint_as_float(u1 & 0xFFFF0000u);
    float l0 = x0 - h0, l1 = x1 - h1;                  // exact
    asm("cvt.rn.bf16x2.f32 %0, %1, %2;" : "=r"(lpack) : "f"(l1), "f"(l0));
}

// ---------------- merged setup: dtype sniff + scratch init + weight prep ----------------
__global__ void k_setup(const unsigned int* __restrict__ topo_u32,
                        const float* __restrict__ w1, const float* __restrict__ Wl,
                        const float* __restrict__ Wr, const float* __restrict__ w2) {
    int i = blockIdx.x * blockDim.x + threadIdx.x;
    if (i == 0) {
        int is64 = 1;
        #pragma unroll 1
        for (int j = 0; j < 32; j++) {
            if (topo_u32[2 * j + 1] != 0u) { is64 = 0; break; }
        }
        g_is64 = is64;
    }
    if (i < NUM_NODES) g_count[i] = 0;
    if (i < CC) { g_sum1[i] = 0.f; g_ssq1[i] = 0.f; }
    if (i < C2) { g_sum2[i] = 0.f; g_ssq2[i] = 0.f; }
    if (i < BB * CC) { g_max1[i] = fNINF(); g_min1[i] = fPINF(); }
    if (i < BB * C2) { g_max2[i] = fNINF(); g_min2[i] = fPINF(); }
    if (i < CC * 384) {
        float v = w1[i];
        __nv_bfloat16 hi = __float2bfloat16(v);
        __nv_bfloat16 lo = __float2bfloat16(v - __bfloat162float(hi));
        ((__nv_bfloat16*)g_w1h4)[i] = hi;
        ((__nv_bfloat16*)g_w1l4)[i] = lo;
    }
    if (i < CC * 256) {
        int co = i >> 8, kp = i & 255;
        float v = (kp < CC) ? Wl[co * CC + kp] : Wr[co * CC + (kp - CC)];
        __nv_bfloat16 hi = __float2bfloat16(v);
        __nv_bfloat16 lo = __float2bfloat16(v - __bfloat162float(hi));
        ((__nv_bfloat16*)g_wsh4)[i] = hi;
        ((__nv_bfloat16*)g_wsl4)[i] = lo;
    }
    if (i < C2 * 768) {
        float v = w2[i];
        __nv_bfloat16 hi = __float2bfloat16(v);
        __nv_bfloat16 lo = __float2bfloat16(v - __bfloat162float(hi));
        ((__nv_bfloat16*)g_w2h4)[i] = hi;
        ((__nv_bfloat16*)g_w2l4)[i] = lo;
    }
}

// ---------------- CSR build (2 edges per thread) ----------------
__global__ void k_hist(const void* __restrict__ topo) {
    int p = blockIdx.x * blockDim.x + threadIdx.x;
    if (p * 2 >= EDGES) return;
    if (g_is64) {
        longlong2 d = __ldg((const longlong2*)((const long long*)topo + EDGES) + p);
        atomicAdd(&g_count[(int)d.x], 1);
        atomicAdd(&g_count[(int)d.y], 1);
    } else {
        int2 d = __ldg((const int2*)((const int*)topo + EDGES) + p);
        atomicAdd(&g_count[d.x], 1);
        atomicAdd(&g_count[d.y], 1);
    }
}

__global__ void k_scan1() {
    __shared__ int sh[256];
    int b = blockIdx.x, t = threadIdx.x;
    int i = b * 256 + t;
    int c = g_count[i];
    sh[t] = c;
    __syncthreads();
    for (int ofs = 1; ofs < 256; ofs <<= 1) {
        int v = (t >= ofs) ? sh[t - ofs] : 0;
        __syncthreads();
        sh[t] += v;
        __syncthreads();
    }
    g_off[i] = sh[t] - c;
    if (t == 255) g_blksum[b] = sh[255];
}

__global__ void k_scan2() {
    __shared__ int sh[256];
    int t = threadIdx.x;
    int c = g_blksum[t];
    sh[t] = c;
    __syncthreads();
    for (int ofs = 1; ofs < 256; ofs <<= 1) {
        int v = (t >= ofs) ? sh[t - ofs] : 0;
        __syncthreads();
        sh[t] += v;
        __syncthreads();
    }
    g_blksum[t] = sh[t] - c;
}

__global__ void k_scan3() {
    int b = blockIdx.x, t = threadIdx.x;
    int i = b * 256 + t;
    int v = g_off[i] + g_blksum[b];
    g_off[i] = v;
    g_cursor[i] = v;
    if (i == NUM_NODES - 1) g_off[NUM_NODES] = EDGES;
}

__global__ void k_scatter(const void* __restrict__ topo) {
    int p = blockIdx.x * blockDim.x + threadIdx.x;
    if (p * 2 >= EDGES) return;
    int s0, s1, d0, d1;
    if (g_is64) {
        longlong2 s = __ldg((const longlong2*)topo + p);
        longlong2 d = __ldg((const longlong2*)((const long long*)topo + EDGES) + p);
        s0 = (int)s.x; s1 = (int)s.y; d0 = (int)d.x; d1 = (int)d.y;
    } else {
        int2 s = __ldg((const int2*)topo + p);
        int2 d = __ldg((const int2*)((const int*)topo + EDGES) + p);
        s0 = s.x; s1 = s.y; d0 = d.x; d1 = d.y;
    }
    int pos0 = atomicAdd(&g_cursor[d0], 1);
    g_src[pos0] = s0;
    int pos1 = atomicAdd(&g_cursor[d1], 1);
    g_src[pos1] = s1;
}

// ---------------- per-node max aggregation (warp per node, 4-edge MLP) ----------------
__global__ __launch_bounds__(256) void k_agg(const float* __restrict__ feat) {
    int gwarp = (blockIdx.x * blockDim.x + threadIdx.x) >> 5;
    int lane = threadIdx.x & 31;
    if (gwarp >= NUM_NODES) return;
    int beg = g_off[gwarp], end = g_off[gwarp + 1];
    float4 acc = make_float4(fNINF(), fNINF(), fNINF(), fNINF());
    int i = beg;
    for (; i + 4 <= end; i += 4) {
        int s0 = g_src[i], s1 = g_src[i + 1], s2 = g_src[i + 2], s3 = g_src[i + 3];
        float4 v0 = __ldg(((const float4*)(feat + (size_t)s0 * CC)) + lane);
        float4 v1 = __ldg(((const float4*)(feat + (size_t)s1 * CC)) + lane);
        float4 v2 = __ldg(((const float4*)(feat + (size_t)s2 * CC)) + lane);
        float4 v3 = __ldg(((const float4*)(feat + (size_t)s3 * CC)) + lane);
        float mx = fmaxf(fmaxf(v0.x, v1.x), fmaxf(v2.x, v3.x));
        float my = fmaxf(fmaxf(v0.y, v1.y), fmaxf(v2.y, v3.y));
        float mz = fmaxf(fmaxf(v0.z, v1.z), fmaxf(v2.z, v3.z));
        float mw = fmaxf(fmaxf(v0.w, v1.w), fmaxf(v2.w, v3.w));
        acc.x = fmaxf(acc.x, mx);
        acc.y = fmaxf(acc.y, my);
        acc.z = fmaxf(acc.z, mz);
        acc.w = fmaxf(acc.w, mw);
    }
    for (; i < end; i++) {
        int s0 = g_src[i];
        float4 v0 = __ldg(((const float4*)(feat + (size_t)s0 * CC)) + lane);
        acc.x = fmaxf(acc.x, v0.x);
        acc.y = fmaxf(acc.y, v0.y);
        acc.z = fmaxf(acc.z, v0.z);
        acc.w = fmaxf(acc.w, v0.w);
    }
    if (beg == end) acc = make_float4(0.f, 0.f, 0.f, 0.f);
    ((float4*)(g_agg + (size_t)gwarp * CC))[lane] = acc;
}

// ---------------- sage via WMMA: D[co][node] = [Wl|Wr] @ [agg;feat], bias + L2-norm ----------------
#define SLDA 72
#define SLDB 136
#define SOFF_X   0         // 128 x 65 floats = 33280B
#define SOFF_AH  33280
#define SOFF_AL  51712
#define SOFF_BH  70144
#define SOFF_BL  87552
#define SM_SAGE_TOTAL 104960
__global__ __launch_bounds__(256) void k_sage(const float* __restrict__ feat,
                                              const float* __restrict__ bl) {
    extern __shared__ char smc[];
    float* shX = (float*)(smc + SOFF_X);
    __nv_bfloat16* shAh = (__nv_bfloat16*)(smc + SOFF_AH);
    __nv_bfloat16* shAl = (__nv_bfloat16*)(smc + SOFF_AL);
    __nv_bfloat16* shBh = (__nv_bfloat16*)(smc + SOFF_BH);
    __nv_bfloat16* shBl = (__nv_bfloat16*)(smc + SOFF_BL);

    int tid = threadIdx.x;
    int wid = tid >> 5;
    int n0 = blockIdx.x * 128;
    int wy = wid & 3, wx = wid >> 2;

    wmma::fragment<wmma::accumulator, 16, 16, 16, float> facc[2][4];
    #pragma unroll
    for (int i = 0; i < 2; i++)
        #pragma unroll
        for (int j = 0; j < 4; j++) wmma::fill_fragment(facc[i][j], 0.f);

    for (int c = 0; c < 4; c++) {
        __syncthreads();
        const float* src = (c < 2) ? (g_agg + (size_t)n0 * CC + c * 64)
                                   : (feat + (size_t)n0 * CC + (c - 2) * 64);
        for (int idx = tid; idx < 128 * 16; idx += 256) {
            int n = idx >> 4, f = idx & 15;
            float4 v = *(const float4*)(src + (size_t)n * CC + f * 4);
            int o = n * 65 + f * 4;
            shX[o] = v.x; shX[o + 1] = v.y; shX[o + 2] = v.z; shX[o + 3] = v.w;
        }
        for (int idx = tid; idx < 1024; idx += 256) {
            int r = idx >> 3, q = idx & 7;
            int gidx = r * 32 + c * 8 + q;
            *(uint4*)(shAh + r * SLDA + q * 8) = g_wsh4[gidx];
            *(uint4*)(shAl + r * SLDA + q * 8) = g_wsl4[gidx];
        }
        __syncthreads();
        // B[kp][n], 2 nodes per iteration (packed)
        for (int idx = tid; idx < 64 * 64; idx += 256) {
            int kp = idx >> 6, p = idx & 63;
            int n = 2 * p;
            float x0 = shX[n * 65 + kp];
            float x1 = shX[(n + 1) * 65 + kp];
            unsigned hp, lp;
            split2(x0, x1, hp, lp);
            *(unsigned*)&shBh[kp * SLDB + n] = hp;
            *(unsigned*)&shBl[kp * SLDB + n] = lp;
        }
        __syncthreads();
        #pragma unroll 1
        for (int ks = 0; ks < 4; ks++) {
            wmma::fragment<wmma::matrix_a, 16, 16, 16, __nv_bfloat16, wmma::row_major> fah[2], fal[2];
            wmma::fragment<wmma::matrix_b, 16, 16, 16, __nv_bfloat16, wmma::row_major> fbh[4], fbl[4];
            #pragma unroll
            for (int i = 0; i < 2; i++) {
                const __nv_bfloat16* pa = shAh + (wy * 32 + i * 16) * SLDA + ks * 16;
                wmma::load_matrix_sync(fah[i], pa, SLDA);
                wmma::load_matrix_sync(fal[i], pa + (SOFF_AL - SOFF_AH) / 2, SLDA);
            }
            #pragma unroll
            for (int j = 0; j < 4; j++) {
                const __nv_bfloat16* pb = shBh + (ks * 16) * SLDB + wx * 64 + j * 16;
                wmma::load_matrix_sync(fbh[j], pb, SLDB);
                wmma::load_matrix_sync(fbl[j], pb + (SOFF_BL - SOFF_BH) / 2, SLDB);
            }
            #pragma unroll
            for (int i = 0; i < 2; i++)
                #pragma unroll
                for (int j = 0; j < 4; j++) {
                    wmma::mma_sync(facc[i][j], fah[i], fbh[j], facc[i][j]);
                    wmma::mma_sync(facc[i][j], fah[i], fbl[j], facc[i][j]);
                    wmma::mma_sync(facc[i][j], fal[i], fbh[j], facc[i][j]);
                }
        }
    }
    __syncthreads();

    float* ep = (float*)smc;
    #pragma unroll
    for (int i = 0; i < 2; i++)
        #pragma unroll
        for (int j = 0; j < 4; j++)
            wmma::store_matrix_sync(ep + (wy * 32 + i * 16) * 132 + wx * 64 + j * 16,
                                    facc[i][j], 132, wmma::mem_row_major);
    __syncthreads();

    if (tid < 128) {
        int n = tid;
        float ss = 0.f;
        #pragma unroll 4
        for (int co = 0; co < CC; co++) {
            float v = ep[co * 132 + n] + bl[co];
            ss += v * v;
        }
        float inv = 1.f / fmaxf(sqrtf(ss), 1e-12f);
        float* dst = g_sage + (size_t)(n0 + n) * CC;
        #pragma unroll 4
        for (int co = 0; co < CC; co += 4) {
            float4 o4;
            o4.x = (ep[(co + 0) * 132 + n] + bl[co + 0]) * inv;
            o4.y = (ep[(co + 1) * 132 + n] + bl[co + 1]) * inv;
            o4.z = (ep[(co + 2) * 132 + n] + bl[co + 2]) * inv;
            o4.w = (ep[(co + 3) * 132 + n] + bl[co + 3]) * inv;
            *(float4*)(dst + co) = o4;
        }
    }
}

// ---------------- unified conv kernel via WMMA, K' = ci*3+k ----------------
// blockIdx.z: 0,1 -> conv2 co-half; 2 -> conv1.
#define LDA 56
#define LDB 136
#define OFF_X   0        // 130 x 17 floats -> pad 8960
#define OFF_AHI 8960     // 128 x LDA bf16 = 14336B
#define OFF_ALO 23296
#define OFF_BHI 37632    // 48 x LDB bf16 = 13056B
#define OFF_BLO 50688    // end 63744
#define SM_CONVW_TOTAL 69632
#define OFF_EP  0        // epilogue: 8 warps x 32 x 68 floats = 69632B (aliases X/A/B after sync)

__global__ __launch_bounds__(256) void k_convs(const float* __restrict__ feat,
                                               const float* __restrict__ b1,
                                               const float* __restrict__ b2) {
    extern __shared__ char smc[];
    float* shX = (float*)(smc + OFF_X);
    __nv_bfloat16* shAhi = (__nv_bfloat16*)(smc + OFF_AHI);
    __nv_bfloat16* shAlo = (__nv_bfloat16*)(smc + OFF_ALO);
    __nv_bfloat16* shBhi = (__nv_bfloat16*)(smc + OFF_BHI);
    __nv_bfloat16* shBlo = (__nv_bfloat16*)(smc + OFF_BLO);

    int tid = threadIdx.x;
    int wid = tid >> 5, lane = tid & 31;
    int l0 = blockIdx.x * 128;
    int b  = blockIdx.y;
    int z  = blockIdx.z;
    bool isc1 = (z == 2);
    int NCH = isc1 ? 8 : 16;
    const uint4* wh4 = isc1 ? g_w1h4 : g_w2h4;
    const uint4* wl4 = isc1 ? g_w1l4 : g_w2l4;
    int co_basew = isc1 ? 0 : z * 128;
    int wstride  = isc1 ? 48 : 96;
    int wy = wid & 3, wx = wid >> 2;

    wmma::fragment<wmma::accumulator, 16, 16, 16, float> facc[2][4];
    #pragma unroll
    for (int i = 0; i < 2; i++)
        #pragma unroll
        for (int j = 0; j < 4; j++) wmma::fill_fragment(facc[i][j], 0.f);

    for (int c = 0; c < NCH; c++) {
        __syncthreads();
        int ci0 = c * 16;
        const float* src = (ci0 < CC) ? (g_sage + (size_t)b * NN * CC + ci0)
                                      : (feat + (size_t)b * NN * CC + (ci0 - CC));
        for (int idx = tid; idx < 130 * 4; idx += 256) {
            int row = idx >> 2, f = idx & 3;
            int gr = l0 + row; if (gr > NN - 1) gr = NN - 1;
            float4 v = *(const float4*)(src + (size_t)gr * CC + f * 4);
            int o = row * 17 + f * 4;
            shX[o] = v.x; shX[o + 1] = v.y; shX[o + 2] = v.z; shX[o + 3] = v.w;
        }
        for (int idx = tid; idx < 768; idx += 256) {
            int r = idx / 6, q = idx - r * 6;
            int gidx = (co_basew + r) * wstride + c * 6 + q;
            *(uint4*)(shAhi + r * LDA + q * 8) = wh4[gidx];
            *(uint4*)(shAlo + r * LDA + q * 8) = wl4[gidx];
        }
        __syncthreads();
        for (int idx = tid; idx < 48 * 64; idx += 256) {
            int kp = idx >> 6, p = idx & 63;
            int l = 2 * p;
            int ci = kp / 3, k = kp - ci * 3;
            float x0 = shX[(l + k) * 17 + ci];
            float x1 = shX[(l + 1 + k) * 17 + ci];
            unsigned hp, lp;
            split2(x0, x1, hp, lp);
            *(unsigned*)&shBhi[kp * LDB + l] = hp;
            *(unsigned*)&shBlo[kp * LDB + l] = lp;
        }
        __syncthreads();
        #pragma unroll 1
        for (int ks = 0; ks < 3; ks++) {
            wmma::fragment<wmma::matrix_a, 16, 16, 16, __nv_bfloat16, wmma::row_major> fah[2], fal[2];
            wmma::fragment<wmma::matrix_b, 16, 16, 16, __nv_bfloat16, wmma::row_major> fbh[4], fbl[4];
            #pragma unroll
            for (int i = 0; i < 2; i++) {
                const __nv_bfloat16* pa = shAhi + (wy * 32 + i * 16) * LDA + ks * 16;
                wmma::load_matrix_sync(fah[i], pa, LDA);
                wmma::load_matrix_sync(fal[i], pa + (OFF_ALO - OFF_AHI) / 2, LDA);
            }
            #pragma unroll
            for (int j = 0; j < 4; j++) {
                const __nv_bfloat16* pb = shBhi + (ks * 16) * LDB + wx * 64 + j * 16;
                wmma::load_matrix_sync(fbh[j], pb, LDB);
                wmma::load_matrix_sync(fbl[j], pb + (OFF_BLO - OFF_BHI) / 2, LDB);
            }
            #pragma unroll
            for (int i = 0; i < 2; i++)
                #pragma unroll
                for (int j = 0; j < 4; j++) {
                    wmma::mma_sync(facc[i][j], fah[i], fbh[j], facc[i][j]);
                    wmma::mma_sync(facc[i][j], fah[i], fbl[j], facc[i][j]);
                    wmma::mma_sync(facc[i][j], fal[i], fbh[j], facc[i][j]);
                }
        }
    }
    __syncthreads();

    float* ep = (float*)(smc + OFF_EP) + wid * (32 * 68);
    #pragma unroll
    for (int i = 0; i < 2; i++)
        #pragma unroll
        for (int j = 0; j < 4; j++)
            wmma::store_matrix_sync(ep + i * 16 * 68 + j * 16, facc[i][j], 68, wmma::mem_row_major);
    __syncwarp();

    {
        int col = wy * 32 + lane;
        float bias = isc1 ? b1[col] : b2[z * 128 + col];
        float mx = fNINF(), mn = fPINF(), s = 0.f, q = 0.f;
        #pragma unroll 4
        for (int l = 0; l < 64; l++) {
            int gl = l0 + wx * 64 + l;
            if (gl <= NN - 3) {
                float v = ep[lane * 68 + l] + bias;
                mx = fmaxf(mx, v); mn = fminf(mn, v);
                s += v; q += v * v;
            }
        }
        if (isc1) {
            int co = col;
            atomicAdd(&g_sum1[co], s);
            atomicAdd(&g_ssq1[co], q);
            atomicMaxF(&g_max1[b * CC + co], mx);
            atomicMinF(&g_min1[b * CC + co], mn);
        } else {
            int co = z * 128 + col;
            atomicAdd(&g_sum2[co], s);
            atomicAdd(&g_ssq2[co], q);
            atomicMaxF(&g_max2[b * C2 + co], mx);
            atomicMinF(&g_min2[b * C2 + co], mn);
        }
    }
}

// ---------------- finish: BN affine + relu + pool + linears + product ----------------
__global__ __launch_bounds__(512) void k_final(const float* __restrict__ g1, const float* __restrict__ be1,
                                               const float* __restrict__ g2, const float* __restrict__ be2,
                                               const float* __restrict__ l1w, const float* __restrict__ l1b,
                                               const float* __restrict__ l2w, const float* __restrict__ l2b,
                                               float* __restrict__ out) {
    __shared__ float p1[BB * CC];
    __shared__ float p2[BB * C2];
    int tid = threadIdx.x;
    const float cnt = (float)(BB * (NN - 2));

    for (int c = tid; c < CC; c += 512) {
        float m = g_sum1[c] / cnt;
        float v = g_ssq1[c] / cnt - m * m;
        float a = g1[c] * rsqrtf(fmaxf(v, 0.f) + 1e-5f);
        float o = be1[c] - a * m;
        for (int b = 0; b < BB; b++) {
            float x = (a >= 0.f) ? g_max1[b * CC + c] : g_min1[b * CC + c];
            p1[b * CC + c] = fmaxf(a * x + o, 0.f);
        }
    }
    for (int c = tid; c < C2; c += 512) {
        float m = g_sum2[c] / cnt;
        float v = g_ssq2[c] / cnt - m * m;
        float a = g2[c] * rsqrtf(fmaxf(v, 0.f) + 1e-5f);
        float o = be2[c] - a * m;
        for (int b = 0; b < BB; b++) {
            float x = (a >= 0.f) ? g_max2[b * C2 + c] : g_min2[b * C2 + c];
            p2[b * C2 + c] = fmaxf(a * x + o, 0.f);
        }
    }
    __syncthreads();
    if (tid < 32) {
        int b = tid >> 1, j = tid & 1;
        float s1 = l1b[j];
        for (int c = 0; c < CC; c++) s1 += p1[b * CC + c] * l1w[j * CC + c];
        float s2 = l2b[j];
        for (int c = 0; c < C2; c++) s2 += p2[b * C2 + c] * l2w[j * C2 + c];
        out[tid] = s1 * s2;
    }
}

// ---------------- host ----------------
extern "C" void kernel_launch(void* const* d_in, const int* in_sizes, int n_in,
                              void* d_out, int out_size) {
    const float* feature = (const float*)d_in[0];
    const void*  topo    = d_in[1];
    const float* lin_l_w = (const float*)d_in[3];
    const float* lin_l_b = (const float*)d_in[4];
    const float* lin_r_w = (const float*)d_in[5];
    const float* conv1_w = (const float*)d_in[6];
    const float* conv1_b = (const float*)d_in[7];
    const float* bn1_g   = (const float*)d_in[8];
    const float* bn1_b   = (const float*)d_in[9];
    const float* conv2_w = (const float*)d_in[10];
    const float* conv2_b = (const float*)d_in[11];
    const float* bn2_g   = (const float*)d_in[12];
    const float* bn2_b   = (const float*)d_in[13];
    const float* lin1_w  = (const float*)d_in[14];
    const float* lin1_b  = (const float*)d_in[15];
    const float* lin2_w  = (const float*)d_in[16];
    const float* lin2_b  = (const float*)d_in[17];
    float* out = (float*)d_out;

    cudaFuncSetAttribute(k_sage,  cudaFuncAttributeMaxDynamicSharedMemorySize, SM_SAGE_TOTAL);
    cudaFuncSetAttribute(k_convs, cudaFuncAttributeMaxDynamicSharedMemorySize, SM_CONVW_TOTAL);

    k_setup<<<768, 256>>>((const unsigned int*)topo, conv1_w, lin_l_w, lin_r_w, conv2_w);
    k_hist<<<EDGES / 512, 256>>>(topo);
    k_scan1<<<256, 256>>>();
    k_scan2<<<1, 256>>>();
    k_scan3<<<256, 256>>>();
    k_scatter<<<EDGES / 512, 256>>>(topo);
    k_agg<<<NUM_NODES / 8, 256>>>(feature);
    k_sage<<<NUM_NODES / 128, 256, SM_SAGE_TOTAL>>>(feature, lin_l_b);
    k_convs<<<dim3(NN / 128, BB, 3), 256, SM_CONVW_TOTAL>>>(feature, conv1_b, conv2_b);
    k_final<<<1, 512>>>(bn1_g, bn1_b, bn2_g, bn2_b,
                        lin1_w, lin1_b, lin2_w, lin2_b, out);
}

// round 17
// speedup vs baseline: 1.1451x; 1.0319x over previous
#include <cuda_runtime.h>
#include <cuda_bf16.h>
#include <mma.h>
#include <math.h>

using namespace nvcuda;

#define BB 16
#define NN 4096
#define CC 128
#define C2 256
#define NUM_NODES 65536
#define EDGES 2097152

// ---------------- device scratch (static, no allocs) ----------------
static __device__ int   g_is64;
static __device__ int   g_count[NUM_NODES];
static __device__ int   g_off[NUM_NODES + 1];
static __device__ int   g_cursor[NUM_NODES];
static __device__ int   g_blksum[256];
static __device__ int   g_src[EDGES];
static __device__ float g_agg[NUM_NODES * CC];
static __device__ float g_sage[NUM_NODES * CC];
static __device__ uint4 g_w1h4[CC * 384 / 8];        // conv1 bf16 hi, [co][k'=ci*3+k]
static __device__ uint4 g_w1l4[CC * 384 / 8];
static __device__ uint4 g_wsh4[CC * 256 / 8];        // sage [Wl|Wr] bf16 hi, [co][k'=256]
static __device__ uint4 g_wsl4[CC * 256 / 8];
static __device__ uint4 g_w2h4[C2 * 768 / 8];        // conv2 bf16 hi, [co][k'=ci*3+k]
static __device__ uint4 g_w2l4[C2 * 768 / 8];
static __device__ float g_sum1[CC],  g_ssq1[CC];
static __device__ float g_max1[BB * CC], g_min1[BB * CC];
static __device__ float g_sum2[C2],  g_ssq2[C2];
static __device__ float g_max2[BB * C2], g_min2[BB * C2];

__device__ __forceinline__ float fNINF() { return __int_as_float(0xff800000u); }
__device__ __forceinline__ float fPINF() { return __int_as_float(0x7f800000u); }

__device__ __forceinline__ void atomicMaxF(float* a, float v) {
    if (v >= 0.f) atomicMax((int*)a, __float_as_int(v));
    else          atomicMin((unsigned int*)a, __float_as_uint(v));
}
__device__ __forceinline__ void atomicMinF(float* a, float v) {
    if (v >= 0.f) atomicMin((int*)a, __float_as_int(v));
    else          atomicMax((unsigned int*)a, __float_as_uint(v));
}

// split 2 floats into packed bf16 hi (truncation) + bf16 lo (rounded residual)
__device__ __forceinline__ void split2(float x0, float x1, unsigned& hpack, unsigned& lpack) {
    unsigned u0 = __float_as_uint(x0), u1 = __float_as_uint(x1);
    hpack = __byte_perm(u0, u1, 0x7632);               // {u1.hi16, u0.hi16}
    float h0 = __uint_as_float(u0 & 0xFFFF0000u);
    float h1 = __uint_as_float(u1 & 0xFFFF0000u);
    float l0 = x0 - h0, l1 = x1 - h1;                  // exact
    asm("cvt.rn.bf16x2.f32 %0, %1, %2;" : "=r"(lpack) : "f"(l1), "f"(l0));
}

// ---------------- merged setup: dtype sniff + scratch init + weight prep ----------------
__global__ void k_setup(const unsigned int* __restrict__ topo_u32,
                        const float* __restrict__ w1, const float* __restrict__ Wl,
                        const float* __restrict__ Wr, const float* __restrict__ w2) {
    int i = blockIdx.x * blockDim.x + threadIdx.x;
    if (i == 0) {
        int is64 = 1;
        #pragma unroll 1
        for (int j = 0; j < 32; j++) {
            if (topo_u32[2 * j + 1] != 0u) { is64 = 0; break; }
        }
        g_is64 = is64;
    }
    if (i < NUM_NODES) g_count[i] = 0;
    if (i < CC) { g_sum1[i] = 0.f; g_ssq1[i] = 0.f; }
    if (i < C2) { g_sum2[i] = 0.f; g_ssq2[i] = 0.f; }
    if (i < BB * CC) { g_max1[i] = fNINF(); g_min1[i] = fPINF(); }
    if (i < BB * C2) { g_max2[i] = fNINF(); g_min2[i] = fPINF(); }
    if (i < CC * 384) {
        float v = w1[i];
        __nv_bfloat16 hi = __float2bfloat16(v);
        __nv_bfloat16 lo = __float2bfloat16(v - __bfloat162float(hi));
        ((__nv_bfloat16*)g_w1h4)[i] = hi;
        ((__nv_bfloat16*)g_w1l4)[i] = lo;
    }
    if (i < CC * 256) {
        int co = i >> 8, kp = i & 255;
        float v = (kp < CC) ? Wl[co * CC + kp] : Wr[co * CC + (kp - CC)];
        __nv_bfloat16 hi = __float2bfloat16(v);
        __nv_bfloat16 lo = __float2bfloat16(v - __bfloat162float(hi));
        ((__nv_bfloat16*)g_wsh4)[i] = hi;
        ((__nv_bfloat16*)g_wsl4)[i] = lo;
    }
    if (i < C2 * 768) {
        float v = w2[i];
        __nv_bfloat16 hi = __float2bfloat16(v);
        __nv_bfloat16 lo = __float2bfloat16(v - __bfloat162float(hi));
        ((__nv_bfloat16*)g_w2h4)[i] = hi;
        ((__nv_bfloat16*)g_w2l4)[i] = lo;
    }
}

// ---------------- CSR build (2 edges per thread) ----------------
__global__ void k_hist(const void* __restrict__ topo) {
    int p = blockIdx.x * blockDim.x + threadIdx.x;
    if (p * 2 >= EDGES) return;
    if (g_is64) {
        longlong2 d = __ldg((const longlong2*)((const long long*)topo + EDGES) + p);
        atomicAdd(&g_count[(int)d.x], 1);
        atomicAdd(&g_count[(int)d.y], 1);
    } else {
        int2 d = __ldg((const int2*)((const int*)topo + EDGES) + p);
        atomicAdd(&g_count[d.x], 1);
        atomicAdd(&g_count[d.y], 1);
    }
}

__global__ void k_scan1() {
    __shared__ int sh[256];
    int b = blockIdx.x, t = threadIdx.x;
    int i = b * 256 + t;
    int c = g_count[i];
    sh[t] = c;
    __syncthreads();
    for (int ofs = 1; ofs < 256; ofs <<= 1) {
        int v = (t >= ofs) ? sh[t - ofs] : 0;
        __syncthreads();
        sh[t] += v;
        __syncthreads();
    }
    g_off[i] = sh[t] - c;
    if (t == 255) g_blksum[b] = sh[255];
}

__global__ void k_scan2() {
    __shared__ int sh[256];
    int t = threadIdx.x;
    int c = g_blksum[t];
    sh[t] = c;
    __syncthreads();
    for (int ofs = 1; ofs < 256; ofs <<= 1) {
        int v = (t >= ofs) ? sh[t - ofs] : 0;
        __syncthreads();
        sh[t] += v;
        __syncthreads();
    }
    g_blksum[t] = sh[t] - c;
}

__global__ void k_scan3() {
    int b = blockIdx.x, t = threadIdx.x;
    int i = b * 256 + t;
    int v = g_off[i] + g_blksum[b];
    g_off[i] = v;
    g_cursor[i] = v;
    if (i == NUM_NODES - 1) g_off[NUM_NODES] = EDGES;
}

__global__ void k_scatter(const void* __restrict__ topo) {
    int p = blockIdx.x * blockDim.x + threadIdx.x;
    if (p * 2 >= EDGES) return;
    int s0, s1, d0, d1;
    if (g_is64) {
        longlong2 s = __ldg((const longlong2*)topo + p);
        longlong2 d = __ldg((const longlong2*)((const long long*)topo + EDGES) + p);
        s0 = (int)s.x; s1 = (int)s.y; d0 = (int)d.x; d1 = (int)d.y;
    } else {
        int2 s = __ldg((const int2*)topo + p);
        int2 d = __ldg((const int2*)((const int*)topo + EDGES) + p);
        s0 = s.x; s1 = s.y; d0 = d.x; d1 = d.y;
    }
    int pos0 = atomicAdd(&g_cursor[d0], 1);
    g_src[pos0] = s0;
    int pos1 = atomicAdd(&g_cursor[d1], 1);
    g_src[pos1] = s1;
}

// ---------------- per-node max aggregation (warp per node, 4-edge MLP) ----------------
__global__ __launch_bounds__(256) void k_agg(const float* __restrict__ feat) {
    int gwarp = (blockIdx.x * blockDim.x + threadIdx.x) >> 5;
    int lane = threadIdx.x & 31;
    if (gwarp >= NUM_NODES) return;
    int beg = g_off[gwarp], end = g_off[gwarp + 1];
    float4 acc = make_float4(fNINF(), fNINF(), fNINF(), fNINF());
    int i = beg;
    for (; i + 4 <= end; i += 4) {
        int s0 = g_src[i], s1 = g_src[i + 1], s2 = g_src[i + 2], s3 = g_src[i + 3];
        float4 v0 = __ldg(((const float4*)(feat + (size_t)s0 * CC)) + lane);
        float4 v1 = __ldg(((const float4*)(feat + (size_t)s1 * CC)) + lane);
        float4 v2 = __ldg(((const float4*)(feat + (size_t)s2 * CC)) + lane);
        float4 v3 = __ldg(((const float4*)(feat + (size_t)s3 * CC)) + lane);
        float mx = fmaxf(fmaxf(v0.x, v1.x), fmaxf(v2.x, v3.x));
        float my = fmaxf(fmaxf(v0.y, v1.y), fmaxf(v2.y, v3.y));
        float mz = fmaxf(fmaxf(v0.z, v1.z), fmaxf(v2.z, v3.z));
        float mw = fmaxf(fmaxf(v0.w, v1.w), fmaxf(v2.w, v3.w));
        acc.x = fmaxf(acc.x, mx);
        acc.y = fmaxf(acc.y, my);
        acc.z = fmaxf(acc.z, mz);
        acc.w = fmaxf(acc.w, mw);
    }
    for (; i < end; i++) {
        int s0 = g_src[i];
        float4 v0 = __ldg(((const float4*)(feat + (size_t)s0 * CC)) + lane);
        acc.x = fmaxf(acc.x, v0.x);
        acc.y = fmaxf(acc.y, v0.y);
        acc.z = fmaxf(acc.z, v0.z);
        acc.w = fmaxf(acc.w, v0.w);
    }
    if (beg == end) acc = make_float4(0.f, 0.f, 0.f, 0.f);
    ((float4*)(g_agg + (size_t)gwarp * CC))[lane] = acc;
}

// ---------------- sage via WMMA: D[co][node] = [Wl|Wr] @ [agg;feat], bias + L2-norm ----------------
#define SLDA 72
#define SLDB 136
#define SOFF_X   0         // 128 x 65 floats = 33280B
#define SOFF_AH  33280
#define SOFF_AL  51712
#define SOFF_BH  70144
#define SOFF_BL  87552
#define SM_SAGE_TOTAL 104960
__global__ __launch_bounds__(256) void k_sage(const float* __restrict__ feat,
                                              const float* __restrict__ bl) {
    extern __shared__ char smc[];
    float* shX = (float*)(smc + SOFF_X);
    __nv_bfloat16* shAh = (__nv_bfloat16*)(smc + SOFF_AH);
    __nv_bfloat16* shAl = (__nv_bfloat16*)(smc + SOFF_AL);
    __nv_bfloat16* shBh = (__nv_bfloat16*)(smc + SOFF_BH);
    __nv_bfloat16* shBl = (__nv_bfloat16*)(smc + SOFF_BL);

    int tid = threadIdx.x;
    int wid = tid >> 5;
    int n0 = blockIdx.x * 128;
    int wy = wid & 3, wx = wid >> 2;

    wmma::fragment<wmma::accumulator, 16, 16, 16, float> facc[2][4];
    #pragma unroll
    for (int i = 0; i < 2; i++)
        #pragma unroll
        for (int j = 0; j < 4; j++) wmma::fill_fragment(facc[i][j], 0.f);

    for (int c = 0; c < 4; c++) {
        __syncthreads();
        const float* src = (c < 2) ? (g_agg + (size_t)n0 * CC + c * 64)
                                   : (feat + (size_t)n0 * CC + (c - 2) * 64);
        for (int idx = tid; idx < 128 * 16; idx += 256) {
            int n = idx >> 4, f = idx & 15;
            float4 v = *(const float4*)(src + (size_t)n * CC + f * 4);
            int o = n * 65 + f * 4;
            shX[o] = v.x; shX[o + 1] = v.y; shX[o + 2] = v.z; shX[o + 3] = v.w;
        }
        for (int idx = tid; idx < 1024; idx += 256) {
            int r = idx >> 3, q = idx & 7;
            int gidx = r * 32 + c * 8 + q;
            *(uint4*)(shAh + r * SLDA + q * 8) = g_wsh4[gidx];
            *(uint4*)(shAl + r * SLDA + q * 8) = g_wsl4[gidx];
        }
        __syncthreads();
        // B[kp][n], 2 nodes per iteration (packed)
        for (int idx = tid; idx < 64 * 64; idx += 256) {
            int kp = idx >> 6, p = idx & 63;
            int n = 2 * p;
            float x0 = shX[n * 65 + kp];
            float x1 = shX[(n + 1) * 65 + kp];
            unsigned hp, lp;
            split2(x0, x1, hp, lp);
            *(unsigned*)&shBh[kp * SLDB + n] = hp;
            *(unsigned*)&shBl[kp * SLDB + n] = lp;
        }
        __syncthreads();
        #pragma unroll 1
        for (int ks = 0; ks < 4; ks++) {
            wmma::fragment<wmma::matrix_a, 16, 16, 16, __nv_bfloat16, wmma::row_major> fah[2], fal[2];
            wmma::fragment<wmma::matrix_b, 16, 16, 16, __nv_bfloat16, wmma::row_major> fbh[4], fbl[4];
            #pragma unroll
            for (int i = 0; i < 2; i++) {
                const __nv_bfloat16* pa = shAh + (wy * 32 + i * 16) * SLDA + ks * 16;
                wmma::load_matrix_sync(fah[i], pa, SLDA);
                wmma::load_matrix_sync(fal[i], pa + (SOFF_AL - SOFF_AH) / 2, SLDA);
            }
            #pragma unroll
            for (int j = 0; j < 4; j++) {
                const __nv_bfloat16* pb = shBh + (ks * 16) * SLDB + wx * 64 + j * 16;
                wmma::load_matrix_sync(fbh[j], pb, SLDB);
                wmma::load_matrix_sync(fbl[j], pb + (SOFF_BL - SOFF_BH) / 2, SLDB);
            }
            #pragma unroll
            for (int i = 0; i < 2; i++)
                #pragma unroll
                for (int j = 0; j < 4; j++) {
                    wmma::mma_sync(facc[i][j], fah[i], fbh[j], facc[i][j]);
                    wmma::mma_sync(facc[i][j], fah[i], fbl[j], facc[i][j]);
                    wmma::mma_sync(facc[i][j], fal[i], fbh[j], facc[i][j]);
                }
        }
    }
    __syncthreads();

    float* ep = (float*)smc;
    #pragma unroll
    for (int i = 0; i < 2; i++)
        #pragma unroll
        for (int j = 0; j < 4; j++)
            wmma::store_matrix_sync(ep + (wy * 32 + i * 16) * 132 + wx * 64 + j * 16,
                                    facc[i][j], 132, wmma::mem_row_major);
    __syncthreads();

    if (tid < 128) {
        int n = tid;
        float ss = 0.f;
        #pragma unroll 4
        for (int co = 0; co < CC; co++) {
            float v = ep[co * 132 + n] + bl[co];
            ss += v * v;
        }
        float inv = 1.f / fmaxf(sqrtf(ss), 1e-12f);
        float* dst = g_sage + (size_t)(n0 + n) * CC;
        #pragma unroll 4
        for (int co = 0; co < CC; co += 4) {
            float4 o4;
            o4.x = (ep[(co + 0) * 132 + n] + bl[co + 0]) * inv;
            o4.y = (ep[(co + 1) * 132 + n] + bl[co + 1]) * inv;
            o4.z = (ep[(co + 2) * 132 + n] + bl[co + 2]) * inv;
            o4.w = (ep[(co + 3) * 132 + n] + bl[co + 3]) * inv;
            *(float4*)(dst + co) = o4;
        }
    }
}

// ---------------- unified conv kernel via WMMA, K' = ci*3+k ----------------
// blockIdx.z: 0,1 -> conv2 co-half; 2 -> conv1.
#define LDA 56
#define LDB 136
#define OFF_X   0        // 130 x 17 floats -> pad 8960
#define OFF_AHI 8960     // 128 x LDA bf16 = 14336B
#define OFF_ALO 23296
#define OFF_BHI 37632    // 48 x LDB bf16 = 13056B
#define OFF_BLO 50688    // end 63744
#define SM_CONVW_TOTAL 69632
#define OFF_EP  0        // epilogue: 8 warps x 32 x 68 floats = 69632B (aliases X/A/B after sync)

__global__ __launch_bounds__(256) void k_convs(const float* __restrict__ feat,
                                               const float* __restrict__ b1,
                                               const float* __restrict__ b2) {
    extern __shared__ char smc[];
    float* shX = (float*)(smc + OFF_X);
    __nv_bfloat16* shAhi = (__nv_bfloat16*)(smc + OFF_AHI);
    __nv_bfloat16* shAlo = (__nv_bfloat16*)(smc + OFF_ALO);
    __nv_bfloat16* shBhi = (__nv_bfloat16*)(smc + OFF_BHI);
    __nv_bfloat16* shBlo = (__nv_bfloat16*)(smc + OFF_BLO);

    int tid = threadIdx.x;
    int wid = tid >> 5, lane = tid & 31;
    int l0 = blockIdx.x * 128;
    int b  = blockIdx.y;
    int z  = blockIdx.z;
    bool isc1 = (z == 2);
    int NCH = isc1 ? 8 : 16;
    const uint4* wh4 = isc1 ? g_w1h4 : g_w2h4;
    const uint4* wl4 = isc1 ? g_w1l4 : g_w2l4;
    int co_basew = isc1 ? 0 : z * 128;
    int wstride  = isc1 ? 48 : 96;
    int wy = wid & 3, wx = wid >> 2;

    wmma::fragment<wmma::accumulator, 16, 16, 16, float> facc[2][4];
    #pragma unroll
    for (int i = 0; i < 2; i++)
        #pragma unroll
        for (int j = 0; j < 4; j++) wmma::fill_fragment(facc[i][j], 0.f);

    for (int c = 0; c < NCH; c++) {
        __syncthreads();
        int ci0 = c * 16;
        const float* src = (ci0 < CC) ? (g_sage + (size_t)b * NN * CC + ci0)
                                      : (feat + (size_t)b * NN * CC + (ci0 - CC));
        for (int idx = tid; idx < 130 * 4; idx += 256) {
            int row = idx >> 2, f = idx & 3;
            int gr = l0 + row; if (gr > NN - 1) gr = NN - 1;
            float4 v = *(const float4*)(src + (size_t)gr * CC + f * 4);
            int o = row * 17 + f * 4;
            shX[o] = v.x; shX[o + 1] = v.y; shX[o + 2] = v.z; shX[o + 3] = v.w;
        }
        for (int idx = tid; idx < 768; idx += 256) {
            int r = idx / 6, q = idx - r * 6;
            int gidx = (co_basew + r) * wstride + c * 6 + q;
            *(uint4*)(shAhi + r * LDA + q * 8) = wh4[gidx];
            *(uint4*)(shAlo + r * LDA + q * 8) = wl4[gidx];
        }
        __syncthreads();
        // B-build with shift reuse: thread handles (ci, p); loads 4 elems, emits 3 rows' packs.
        // row kp=3ci+k, pack p covers cols (2p,2p+1) = {X[2p+k][ci], X[2p+1+k][ci]}
        for (int idx = tid; idx < 16 * 64; idx += 256) {
            int ci = idx >> 6, p = idx & 63;
            int l = 2 * p;
            float x0 = shX[(l + 0) * 17 + ci];
            float x1 = shX[(l + 1) * 17 + ci];
            float x2 = shX[(l + 2) * 17 + ci];
            float x3 = shX[(l + 3) * 17 + ci];
            unsigned u0 = __float_as_uint(x0), u1 = __float_as_uint(x1);
            unsigned u2 = __float_as_uint(x2), u3 = __float_as_uint(x3);
            unsigned h01 = __byte_perm(u0, u1, 0x7632);
            unsigned h12 = __byte_perm(u1, u2, 0x7632);
            unsigned h23 = __byte_perm(u2, u3, 0x7632);
            float t0 = x0 - __uint_as_float(u0 & 0xFFFF0000u);
            float t1 = x1 - __uint_as_float(u1 & 0xFFFF0000u);
            float t2 = x2 - __uint_as_float(u2 & 0xFFFF0000u);
            float t3 = x3 - __uint_as_float(u3 & 0xFFFF0000u);
            unsigned l01, l12, l23;
            asm("cvt.rn.bf16x2.f32 %0, %1, %2;" : "=r"(l01) : "f"(t1), "f"(t0));
            asm("cvt.rn.bf16x2.f32 %0, %1, %2;" : "=r"(l12) : "f"(t2), "f"(t1));
            asm("cvt.rn.bf16x2.f32 %0, %1, %2;" : "=r"(l23) : "f"(t3), "f"(t2));
            int r0 = 3 * ci;
            *(unsigned*)&shBhi[(r0 + 0) * LDB + l] = h01;
            *(unsigned*)&shBhi[(r0 + 1) * LDB + l] = h12;
            *(unsigned*)&shBhi[(r0 + 2) * LDB + l] = h23;
            *(unsigned*)&shBlo[(r0 + 0) * LDB + l] = l01;
            *(unsigned*)&shBlo[(r0 + 1) * LDB + l] = l12;
            *(unsigned*)&shBlo[(r0 + 2) * LDB + l] = l23;
        }
        __syncthreads();
        #pragma unroll 1
        for (int ks = 0; ks < 3; ks++) {
            wmma::fragment<wmma::matrix_a, 16, 16, 16, __nv_bfloat16, wmma::row_major> fah[2], fal[2];
            wmma::fragment<wmma::matrix_b, 16, 16, 16, __nv_bfloat16, wmma::row_major> fbh[4], fbl[4];
            #pragma unroll
            for (int i = 0; i < 2; i++) {
                const __nv_bfloat16* pa = shAhi + (wy * 32 + i * 16) * LDA + ks * 16;
                wmma::load_matrix_sync(fah[i], pa, LDA);
                wmma::load_matrix_sync(fal[i], pa + (OFF_ALO - OFF_AHI) / 2, LDA);
            }
            #pragma unroll
            for (int j = 0; j < 4; j++) {
                const __nv_bfloat16* pb = shBhi + (ks * 16) * LDB + wx * 64 + j * 16;
                wmma::load_matrix_sync(fbh[j], pb, LDB);
                wmma::load_matrix_sync(fbl[j], pb + (OFF_BLO - OFF_BHI) / 2, LDB);
            }
            #pragma unroll
            for (int i = 0; i < 2; i++)
                #pragma unroll
                for (int j = 0; j < 4; j++) {
                    wmma::mma_sync(facc[i][j], fah[i], fbh[j], facc[i][j]);
                    wmma::mma_sync(facc[i][j], fah[i], fbl[j], facc[i][j]);
                    wmma::mma_sync(facc[i][j], fal[i], fbh[j], facc[i][j]);
                }
        }
    }
    __syncthreads();

    float* ep = (float*)(smc + OFF_EP) + wid * (32 * 68);
    #pragma unroll
    for (int i = 0; i < 2; i++)
        #pragma unroll
        for (int j = 0; j < 4; j++)
            wmma::store_matrix_sync(ep + i * 16 * 68 + j * 16, facc[i][j], 68, wmma::mem_row_major);
    __syncwarp();

    {
        int col = wy * 32 + lane;
        float bias = isc1 ? b1[col] : b2[z * 128 + col];
        float mx = fNINF(), mn = fPINF(), s = 0.f, q = 0.f;
        #pragma unroll 4
        for (int l = 0; l < 64; l++) {
            int gl = l0 + wx * 64 + l;
            if (gl <= NN - 3) {
                float v = ep[lane * 68 + l] + bias;
                mx = fmaxf(mx, v); mn = fminf(mn, v);
                s += v; q += v * v;
            }
        }
        if (isc1) {
            int co = col;
            atomicAdd(&g_sum1[co], s);
            atomicAdd(&g_ssq1[co], q);
            atomicMaxF(&g_max1[b * CC + co], mx);
            atomicMinF(&g_min1[b * CC + co], mn);
        } else {
            int co = z * 128 + col;
            atomicAdd(&g_sum2[co], s);
            atomicAdd(&g_ssq2[co], q);
            atomicMaxF(&g_max2[b * C2 + co], mx);
            atomicMinF(&g_min2[b * C2 + co], mn);
        }
    }
}

// ---------------- finish: BN affine + relu + pool + linears + product ----------------
__global__ __launch_bounds__(512) void k_final(const float* __restrict__ g1, const float* __restrict__ be1,
                                               const float* __restrict__ g2, const float* __restrict__ be2,
                                               const float* __restrict__ l1w, const float* __restrict__ l1b,
                                               const float* __restrict__ l2w, const float* __restrict__ l2b,
                                               float* __restrict__ out) {
    __shared__ float p1[BB * CC];
    __shared__ float p2[BB * C2];
    int tid = threadIdx.x;
    const float cnt = (float)(BB * (NN - 2));

    for (int c = tid; c < CC; c += 512) {
        float m = g_sum1[c] / cnt;
        float v = g_ssq1[c] / cnt - m * m;
        float a = g1[c] * rsqrtf(fmaxf(v, 0.f) + 1e-5f);
        float o = be1[c] - a * m;
        for (int b = 0; b < BB; b++) {
            float x = (a >= 0.f) ? g_max1[b * CC + c] : g_min1[b * CC + c];
            p1[b * CC + c] = fmaxf(a * x + o, 0.f);
        }
    }
    for (int c = tid; c < C2; c += 512) {
        float m = g_sum2[c] / cnt;
        float v = g_ssq2[c] / cnt - m * m;
        float a = g2[c] * rsqrtf(fmaxf(v, 0.f) + 1e-5f);
        float o = be2[c] - a * m;
        for (int b = 0; b < BB; b++) {
            float x = (a >= 0.f) ? g_max2[b * C2 + c] : g_min2[b * C2 + c];
            p2[b * C2 + c] = fmaxf(a * x + o, 0.f);
        }
    }
    __syncthreads();
    if (tid < 32) {
        int b = tid >> 1, j = tid & 1;
        float s1 = l1b[j];
        for (int c = 0; c < CC; c++) s1 += p1[b * CC + c] * l1w[j * CC + c];
        float s2 = l2b[j];
        for (int c = 0; c < C2; c++) s2 += p2[b * C2 + c] * l2w[j * C2 + c];
        out[tid] = s1 * s2;
    }
}

// ---------------- host ----------------
extern "C" void kernel_launch(void* const* d_in, const int* in_sizes, int n_in,
                              void* d_out, int out_size) {
    const float* feature = (const float*)d_in[0];
    const void*  topo    = d_in[1];
    const float* lin_l_w = (const float*)d_in[3];
    const float* lin_l_b = (const float*)d_in[4];
    const float* lin_r_w = (const float*)d_in[5];
    const float* conv1_w = (const float*)d_in[6];
    const float* conv1_b = (const float*)d_in[7];
    const float* bn1_g   = (const float*)d_in[8];
    const float* bn1_b   = (const float*)d_in[9];
    const float* conv2_w = (const float*)d_in[10];
    const float* conv2_b = (const float*)d_in[11];
    const float* bn2_g   = (const float*)d_in[12];
    const float* bn2_b   = (const float*)d_in[13];
    const float* lin1_w  = (const float*)d_in[14];
    const float* lin1_b  = (const float*)d_in[15];
    const float* lin2_w  = (const float*)d_in[16];
    const float* lin2_b  = (const float*)d_in[17];
    float* out = (float*)d_out;

    cudaFuncSetAttribute(k_sage,  cudaFuncAttributeMaxDynamicSharedMemorySize, SM_SAGE_TOTAL);
    cudaFuncSetAttribute(k_convs, cudaFuncAttributeMaxDynamicSharedMemorySize, SM_CONVW_TOTAL);

    k_setup<<<768, 256>>>((const unsigned int*)topo, conv1_w, lin_l_w, lin_r_w, conv2_w);
    k_hist<<<EDGES / 512, 256>>>(topo);
    k_scan1<<<256, 256>>>();
    k_scan2<<<1, 256>>>();
    k_scan3<<<256, 256>>>();
    k_scatter<<<EDGES / 512, 256>>>(topo);
    k_agg<<<NUM_NODES / 8, 256>>>(feature);
    k_sage<<<NUM_NODES / 128, 256, SM_SAGE_TOTAL>>>(feature, lin_l_b);
    k_convs<<<dim3(NN / 128, BB, 3), 256, SM_CONVW_TOTAL>>>(feature, conv1_b, conv2_b);
    k_final<<<1, 512>>>(bn1_g, bn1_b, bn2_g, bn2_b,
                        lin1_w, lin1_b, lin2_w, lin2_b, out);
}